// round 6
// baseline (speedup 1.0000x reference)
#include <cuda_runtime.h>
#include <cstdint>
#include <cstddef>

// Problem constants
#define HH   32
#define NQ   2048
#define TT   2048
#define DD   128
#define RRNK 64
#define KAUG 192   // 128 (quant key / q) + 64 (sign / proj)

// Scratch: augmented tf32-rounded operands, K-PERMUTED within 32-float chunks
// so gemm fragment loads are contiguous float4s.
// perm(k) = (k & ~31) | ((k&3)*8 + ((k&31)>>2))
__device__ __align__(16) float g_Aaug[(size_t)HH * NQ * KAUG];
__device__ __align__(16) float g_Baug[(size_t)HH * TT * KAUG];

__device__ __forceinline__ int permk(int d) {
    const int w = d & 31;
    return (d & ~31) | ((w & 3) * 8 + (w >> 2));
}

__device__ __forceinline__ float to_tf32(float x) {
    unsigned u;
    asm("cvt.rna.tf32.f32 %0, %1;" : "=r"(u) : "f"(x));
    return __uint_as_float(u);
}
__device__ __forceinline__ float sgnf(float x) {
    return (x > 0.0f) ? 1.0f : ((x < 0.0f) ? -1.0f : 0.0f);
}

// ---------------------------------------------------------------------------
// Prep: tensor-core JL projection + permuted operand build.
// grid (16 mtiles, 32 heads, 2 modes), 256 threads.
// ---------------------------------------------------------------------------
#define PREP_SMEM_BYTES ((128 * 132 + 64 * 132) * 4)

__global__ __launch_bounds__(256)
void prep_mma_kernel(const float* __restrict__ q,
                     const float* __restrict__ ko,
                     const float* __restrict__ kq,
                     const float* __restrict__ G) {
    extern __shared__ float psm[];
    float* Vs = psm;              // [128][132]
    float* Gs = psm + 128 * 132;  // [64][132]

    const int tid  = threadIdx.x;
    const int mt   = blockIdx.x;
    const int h    = blockIdx.y;
    const int mode = blockIdx.z;
    const size_t row0 = (size_t)h * 2048 + (size_t)mt * 128;

    for (int idx = tid; idx < 128 * 64; idx += 256) {
        const int d = idx >> 6, r = idx & 63;
        Gs[r * 132 + d] = to_tf32(G[idx]);
    }
    if (mode == 0) {
        for (int idx = tid; idx < 128 * 128; idx += 256) {
            const int r = idx >> 7, d = idx & 127;
            const float tv = to_tf32(q[(row0 + r) * DD + d]);
            Vs[r * 132 + d] = tv;
            g_Aaug[(row0 + r) * KAUG + permk(d)] = tv;
        }
    } else {
        for (int idx = tid; idx < 128 * 128; idx += 256) {
            const int r = idx >> 7, d = idx & 127;
            const size_t gi = (row0 + r) * DD + d;
            const float a = ko[gi], b = kq[gi];
            Vs[r * 132 + d] = to_tf32(a - b);
            g_Baug[(row0 + r) * KAUG + permk(d)] = to_tf32(b);
        }
    }
    __syncthreads();

    const int wid = tid >> 5, lane = tid & 31;
    const int g = lane >> 2, t4 = lane & 3;

    float c[8][4];
    #pragma unroll
    for (int j = 0; j < 8; j++)
        #pragma unroll
        for (int k = 0; k < 4; k++) c[j][k] = 0.0f;

    #pragma unroll 2
    for (int k0 = 0; k0 < 128; k0 += 8) {
        unsigned a[4];
        const float* p0 = Vs + (wid * 16 + g) * 132 + k0 + t4;
        const float* p1 = p0 + 8 * 132;
        a[0] = __float_as_uint(p0[0]);
        a[1] = __float_as_uint(p1[0]);
        a[2] = __float_as_uint(p0[4]);
        a[3] = __float_as_uint(p1[4]);
        #pragma unroll
        for (int jn = 0; jn < 8; jn++) {
            const float* pb = Gs + (jn * 8 + g) * 132 + k0 + t4;
            const unsigned b0 = __float_as_uint(pb[0]);
            const unsigned b1 = __float_as_uint(pb[4]);
            asm volatile(
                "mma.sync.aligned.m16n8k8.row.col.f32.tf32.tf32.f32 "
                "{%0,%1,%2,%3}, {%4,%5,%6,%7}, {%8,%9}, {%0,%1,%2,%3};"
                : "+f"(c[jn][0]), "+f"(c[jn][1]), "+f"(c[jn][2]), "+f"(c[jn][3])
                : "r"(a[0]), "r"(a[1]), "r"(a[2]), "r"(a[3]),
                  "r"(b0), "r"(b1));
        }
    }

    const size_t rg = row0 + wid * 16 + g;
    #pragma unroll
    for (int jn = 0; jn < 8; jn++) {
        const int col = 128 + jn * 8 + 2 * t4;   // and col+1
        const int p0c = permk(col), p1c = permk(col + 1);
        if (mode == 0) {
            const float sc = 1.0f / 64.0f;       // (1/sqrt(R)) * alpha
            g_Aaug[rg * KAUG + p0c]       = to_tf32(c[jn][0] * sc);
            g_Aaug[rg * KAUG + p1c]       = to_tf32(c[jn][1] * sc);
            g_Aaug[(rg + 8) * KAUG + p0c] = to_tf32(c[jn][2] * sc);
            g_Aaug[(rg + 8) * KAUG + p1c] = to_tf32(c[jn][3] * sc);
        } else {
            g_Baug[rg * KAUG + p0c]       = sgnf(c[jn][0]);
            g_Baug[rg * KAUG + p1c]       = sgnf(c[jn][1]);
            g_Baug[(rg + 8) * KAUG + p0c] = sgnf(c[jn][2]);
            g_Baug[(rg + 8) * KAUG + p1c] = sgnf(c[jn][3]);
        }
    }
}

// ---------------------------------------------------------------------------
// Main GEMM: out[h] = A'[h](2048x192) * B'[h]^T, fp32.
// CTA tile 128x128; K in 6 chunks of 32 floats, cp.async double-buffered
// (2 CTAs/SM). Warp tile 64x32 tf32 mma; fragment loads are LDS.128 thanks
// to the prep-side K permutation (24 LDS.128 per warp-chunk vs 96 LDS.32).
// ---------------------------------------------------------------------------
#define KC     32
#define ROWP   36
#define BUFSZ  (128 * ROWP)                 // floats per tensor per buffer
#define GEMM_SMEM_BYTES (4 * BUFSZ * 4)     // 73728 bytes

__global__ __launch_bounds__(256, 2)
void gemm_kernel(float* __restrict__ out) {
    extern __shared__ float sm[];
    // A buf b: sm + b*BUFSZ ; B buf b: sm + 2*BUFSZ + b*BUFSZ

    const int h  = blockIdx.z;
    const int mt = blockIdx.y;
    const int nt = blockIdx.x;
    const float* Ag = g_Aaug + ((size_t)h * NQ + (size_t)mt * 128) * KAUG;
    const float* Bg = g_Baug + ((size_t)h * TT + (size_t)nt * 128) * KAUG;

    const int tid = threadIdx.x;

    auto prefetch = [&](int chunk, int buf) {
        #pragma unroll
        for (int i = 0; i < 8; i++) {
            const int id   = i * 256 + tid;     // 0..2047
            const int bsel = id >> 10;          // 0 = A, 1 = B
            const int rid  = id & 1023;
            const int row  = rid >> 3;
            const int c0   = (rid & 7) * 4;
            float* dst = sm + bsel * 2 * BUFSZ + buf * BUFSZ + row * ROWP + c0;
            const float* src = (bsel ? Bg : Ag) + (size_t)row * KAUG + chunk * KC + c0;
            const unsigned sdst = (unsigned)__cvta_generic_to_shared(dst);
            asm volatile("cp.async.cg.shared.global [%0], [%1], 16;"
                         :: "r"(sdst), "l"(src));
        }
    };

    const int wid  = tid >> 5;
    const int lane = tid & 31;
    const int wm   = wid >> 2;      // 0..1
    const int wn   = wid & 3;       // 0..3
    const int g    = lane >> 2;
    const int t4   = lane & 3;

    float c[4][4][4];
    #pragma unroll
    for (int im = 0; im < 4; im++)
        #pragma unroll
        for (int jn = 0; jn < 4; jn++)
            #pragma unroll
            for (int k = 0; k < 4; k++) c[im][jn][k] = 0.0f;

    prefetch(0, 0);
    asm volatile("cp.async.commit_group;");

    for (int ch = 0; ch < 6; ch++) {
        if (ch < 5) {
            prefetch(ch + 1, (ch + 1) & 1);
            asm volatile("cp.async.commit_group;");
            asm volatile("cp.async.wait_group 1;");
        } else {
            asm volatile("cp.async.wait_group 0;");
        }
        __syncthreads();

        const float* As = sm + (ch & 1) * BUFSZ;
        const float* Bs = sm + 2 * BUFSZ + (ch & 1) * BUFSZ;

        #pragma unroll
        for (int hf = 0; hf < 2; hf++) {
            // Vectorized fragment loads: all operands for 2 k8-steps.
            float4 va0[4], va1[4], vb[4];
            #pragma unroll
            for (int im = 0; im < 4; im++) {
                const float* p = As + (wm * 64 + im * 16 + g) * ROWP + t4 * 8 + hf * 4;
                va0[im] = *(const float4*)p;
                va1[im] = *(const float4*)(p + 8 * ROWP);
            }
            #pragma unroll
            for (int jn = 0; jn < 4; jn++) {
                const float* p = Bs + (wn * 32 + jn * 8 + g) * ROWP + t4 * 8 + hf * 4;
                vb[jn] = *(const float4*)p;
            }
            #pragma unroll
            for (int s = 0; s < 2; s++) {
                #pragma unroll
                for (int im = 0; im < 4; im++) {
                    const float* f0 = &va0[im].x;
                    const float* f1 = &va1[im].x;
                    const unsigned a0 = __float_as_uint(f0[2 * s]);
                    const unsigned a1 = __float_as_uint(f1[2 * s]);
                    const unsigned a2 = __float_as_uint(f0[2 * s + 1]);
                    const unsigned a3 = __float_as_uint(f1[2 * s + 1]);
                    #pragma unroll
                    for (int jn = 0; jn < 4; jn++) {
                        const float* fb = &vb[jn].x;
                        const unsigned b0 = __float_as_uint(fb[2 * s]);
                        const unsigned b1 = __float_as_uint(fb[2 * s + 1]);
                        asm volatile(
                            "mma.sync.aligned.m16n8k8.row.col.f32.tf32.tf32.f32 "
                            "{%0,%1,%2,%3}, {%4,%5,%6,%7}, {%8,%9}, {%0,%1,%2,%3};"
                            : "+f"(c[im][jn][0]), "+f"(c[im][jn][1]),
                              "+f"(c[im][jn][2]), "+f"(c[im][jn][3])
                            : "r"(a0), "r"(a1), "r"(a2), "r"(a3),
                              "r"(b0), "r"(b1));
                    }
                }
            }
        }
        __syncthreads();
    }

    // Epilogue: float2 stores
    float* C = out + ((size_t)h * NQ + (size_t)mt * 128) * (size_t)TT + (size_t)nt * 128;
    #pragma unroll
    for (int im = 0; im < 4; im++) {
        const int row = wm * 64 + im * 16 + g;
        #pragma unroll
        for (int jn = 0; jn < 4; jn++) {
            const int col = wn * 32 + jn * 8 + 2 * t4;
            float2 v0; v0.x = c[im][jn][0]; v0.y = c[im][jn][1];
            float2 v1; v1.x = c[im][jn][2]; v1.y = c[im][jn][3];
            *(float2*)(C + (size_t)row * TT + col)       = v0;
            *(float2*)(C + (size_t)(row + 8) * TT + col) = v1;
        }
    }
}

// ---------------------------------------------------------------------------
extern "C" void kernel_launch(void* const* d_in, const int* in_sizes, int n_in,
                              void* d_out, int out_size) {
    const float* q  = (const float*)d_in[0];   // (1,32,2048,128)
    const float* ko = (const float*)d_in[1];   // (1,32,2048,128)
    const float* kq = (const float*)d_in[2];   // (1,32,2048,128)
    const float* G  = (const float*)d_in[3];   // (128,64)
    float* out = (float*)d_out;                // (1,32,2048,2048)

    cudaFuncSetAttribute(prep_mma_kernel,
                         cudaFuncAttributeMaxDynamicSharedMemorySize,
                         PREP_SMEM_BYTES);
    dim3 pgrid(16, 32, 2);
    prep_mma_kernel<<<pgrid, 256, PREP_SMEM_BYTES>>>(q, ko, kq, G);

    cudaFuncSetAttribute(gemm_kernel,
                         cudaFuncAttributeMaxDynamicSharedMemorySize,
                         GEMM_SMEM_BYTES);
    dim3 grid(TT / 128, NQ / 128, HH);
    gemm_kernel<<<grid, 256, GEMM_SMEM_BYTES>>>(out);
}

// round 10
// speedup vs baseline: 1.8099x; 1.8099x over previous
#include <cuda_runtime.h>
#include <cuda_fp16.h>
#include <cstdint>
#include <cstddef>

// Problem constants
#define HH   32
#define NQ   2048
#define TT   2048
#define DD   128
#define RRNK 64
#define KAUG 192   // 128 (quant key / q) + 64 (sign / proj)

// Scratch: augmented fp16 operands.
// A'[h][n][0:128]=h(q),       A'[h][n][128+r]=h((q@G)_r/64)
// B'[h][t][0:128]=h(k_quant), B'[h][t][128+r]=sign((k_orig-k_quant)@G)_r
__device__ __align__(16) __half g_Aaug[(size_t)HH * NQ * KAUG];
__device__ __align__(16) __half g_Baug[(size_t)HH * TT * KAUG];

__device__ __forceinline__ float to_tf32(float x) {
    unsigned u;
    asm("cvt.rna.tf32.f32 %0, %1;" : "=r"(u) : "f"(x));
    return __uint_as_float(u);
}
__device__ __forceinline__ float sgnf(float x) {
    return (x > 0.0f) ? 1.0f : ((x < 0.0f) ? -1.0f : 0.0f);
}

// ---------------------------------------------------------------------------
// Prep: tf32 tensor-core JL projection, fp16 operand build.
// grid (16 mtiles, 32 heads, 2 modes), 256 threads.
// ---------------------------------------------------------------------------
#define PREP_SMEM_BYTES ((128 * 132 + 64 * 132) * 4)

__global__ __launch_bounds__(256)
void prep_mma_kernel(const float* __restrict__ q,
                     const float* __restrict__ ko,
                     const float* __restrict__ kq,
                     const float* __restrict__ G) {
    extern __shared__ float psm[];
    float* Vs = psm;              // [128][132] staged vectors (tf32)
    float* Gs = psm + 128 * 132;  // [64][132]  G transposed   (tf32)

    const int tid  = threadIdx.x;
    const int mt   = blockIdx.x;
    const int h    = blockIdx.y;
    const int mode = blockIdx.z;              // 0 = A-side(q), 1 = B-side(keys)
    const size_t row0 = (size_t)h * 2048 + (size_t)mt * 128;

    // Stage G transposed: Gs[r][d] = tf32(G[d][r])
    for (int idx = tid; idx < 128 * 64; idx += 256) {
        const int d = idx >> 6, r = idx & 63;
        Gs[r * 132 + d] = to_tf32(G[idx]);
    }
    // Stage vectors + emit fp16 head part of augmented rows (half2 writes)
    if (mode == 0) {
        for (int idx = tid; idx < 128 * 64; idx += 256) {
            const int r = idx >> 6, d2 = idx & 63;
            const float2 v = *(const float2*)&q[(row0 + r) * DD + 2 * d2];
            Vs[r * 132 + 2 * d2]     = to_tf32(v.x);
            Vs[r * 132 + 2 * d2 + 1] = to_tf32(v.y);
            *(__half2*)&g_Aaug[(row0 + r) * KAUG + 2 * d2] = __floats2half2_rn(v.x, v.y);
        }
    } else {
        for (int idx = tid; idx < 128 * 64; idx += 256) {
            const int r = idx >> 6, d2 = idx & 63;
            const size_t gi = (row0 + r) * DD + 2 * d2;
            const float2 a = *(const float2*)&ko[gi];
            const float2 b = *(const float2*)&kq[gi];
            Vs[r * 132 + 2 * d2]     = to_tf32(a.x - b.x);   // residual e
            Vs[r * 132 + 2 * d2 + 1] = to_tf32(a.y - b.y);
            *(__half2*)&g_Baug[(row0 + r) * KAUG + 2 * d2] = __floats2half2_rn(b.x, b.y);
        }
    }
    __syncthreads();

    const int wid = tid >> 5, lane = tid & 31;
    const int g = lane >> 2, t4 = lane & 3;

    float c[8][4];
    #pragma unroll
    for (int j = 0; j < 8; j++)
        #pragma unroll
        for (int k = 0; k < 4; k++) c[j][k] = 0.0f;

    #pragma unroll 2
    for (int k0 = 0; k0 < 128; k0 += 8) {
        unsigned a[4];
        const float* p0 = Vs + (wid * 16 + g) * 132 + k0 + t4;
        const float* p1 = p0 + 8 * 132;
        a[0] = __float_as_uint(p0[0]);
        a[1] = __float_as_uint(p1[0]);
        a[2] = __float_as_uint(p0[4]);
        a[3] = __float_as_uint(p1[4]);
        #pragma unroll
        for (int jn = 0; jn < 8; jn++) {
            const float* pb = Gs + (jn * 8 + g) * 132 + k0 + t4;
            const unsigned b0 = __float_as_uint(pb[0]);
            const unsigned b1 = __float_as_uint(pb[4]);
            asm volatile(
                "mma.sync.aligned.m16n8k8.row.col.f32.tf32.tf32.f32 "
                "{%0,%1,%2,%3}, {%4,%5,%6,%7}, {%8,%9}, {%0,%1,%2,%3};"
                : "+f"(c[jn][0]), "+f"(c[jn][1]), "+f"(c[jn][2]), "+f"(c[jn][3])
                : "r"(a[0]), "r"(a[1]), "r"(a[2]), "r"(a[3]),
                  "r"(b0), "r"(b1));
        }
    }

    // Tail epilogue: half2 writes (col even -> aligned)
    const size_t rg = row0 + wid * 16 + g;
    #pragma unroll
    for (int jn = 0; jn < 8; jn++) {
        const int col = 128 + jn * 8 + 2 * t4;
        if (mode == 0) {
            const float sc = 1.0f / 64.0f;   // (1/sqrt(R)) * alpha
            *(__half2*)&g_Aaug[rg * KAUG + col] =
                __floats2half2_rn(c[jn][0] * sc, c[jn][1] * sc);
            *(__half2*)&g_Aaug[(rg + 8) * KAUG + col] =
                __floats2half2_rn(c[jn][2] * sc, c[jn][3] * sc);
        } else {
            *(__half2*)&g_Baug[rg * KAUG + col] =
                __floats2half2_rn(sgnf(c[jn][0]), sgnf(c[jn][1]));
            *(__half2*)&g_Baug[(rg + 8) * KAUG + col] =
                __floats2half2_rn(sgnf(c[jn][2]), sgnf(c[jn][3]));
        }
    }
}

// ---------------------------------------------------------------------------
// Main GEMM (fp16): out[h] = A'[h](2048x192) * B'[h]^T, fp32 accum.
// CTA tile 128x128; K in 3 chunks of 64 halfs (128B rows), cp.async
// double-buffered (72KB smem -> 2 CTAs/SM). Warp tile 64x32 via
// mma.m16n8k16.f16, fragments via ldmatrix.x4. Row pitch 144B = 36 words
// -> ldmatrix rows hit banks 4r mod 32: conflict-free.
// ---------------------------------------------------------------------------
#define KCH    64                          // halfs per chunk
#define ROWPH  72                          // halfs per padded row (144 B)
#define ABUFH  (128 * ROWPH)               // halfs per tensor per buffer
#define GEMM_SMEM_BYTES (4 * ABUFH * 2)    // 73728 bytes

__global__ __launch_bounds__(256, 2)
void gemm_kernel(float* __restrict__ out) {
    extern __shared__ __half smh[];
    // A buf b: smh + b*ABUFH ; B buf b: smh + 2*ABUFH + b*ABUFH
    const unsigned smem_u32 = (unsigned)__cvta_generic_to_shared(smh);

    const int h  = blockIdx.z;
    const int mt = blockIdx.y;
    const int nt = blockIdx.x;
    const __half* Ag = g_Aaug + ((size_t)h * NQ + (size_t)mt * 128) * KAUG;
    const __half* Bg = g_Baug + ((size_t)h * TT + (size_t)nt * 128) * KAUG;

    const int tid = threadIdx.x;

    auto prefetch = [&](int chunk, int buf) {
        #pragma unroll
        for (int i = 0; i < 8; i++) {
            const int id   = i * 256 + tid;     // 0..2047 granules of 16B
            const int isB  = id >> 10;          // 0 = A, 1 = B
            const int rid  = id & 1023;
            const int row  = rid >> 3;
            const int g16  = rid & 7;           // 16B granule within 128B row
            __half* dst = smh + isB * 2 * ABUFH + buf * ABUFH + row * ROWPH + g16 * 8;
            const __half* src = (isB ? Bg : Ag) + (size_t)row * KAUG + chunk * KCH + g16 * 8;
            const unsigned sdst = (unsigned)__cvta_generic_to_shared(dst);
            asm volatile("cp.async.cg.shared.global [%0], [%1], 16;"
                         :: "r"(sdst), "l"(src));
        }
    };

    const int wid  = tid >> 5;
    const int lane = tid & 31;
    const int wm   = wid >> 2;      // 0..1 -> 64-row band
    const int wn   = wid & 3;       // 0..3 -> 32-col band
    const int g    = lane >> 2;
    const int t4   = lane & 3;

    // ldmatrix lane address components (in halfs)
    const int mi = lane >> 3;       // matrix index 0..3
    const int l7 = lane & 7;
    const unsigned a_lane = ((mi & 1) * 8 + l7) * ROWPH + (mi >> 1) * 8;
    const unsigned b_lane = ((mi >> 1) * 8 + l7) * ROWPH + (mi & 1) * 8;

    float c[4][4][4];
    #pragma unroll
    for (int im = 0; im < 4; im++)
        #pragma unroll
        for (int jn = 0; jn < 4; jn++)
            #pragma unroll
            for (int k = 0; k < 4; k++) c[im][jn][k] = 0.0f;

    prefetch(0, 0);
    asm volatile("cp.async.commit_group;");

    for (int ch = 0; ch < 3; ch++) {
        if (ch < 2) {
            prefetch(ch + 1, (ch + 1) & 1);
            asm volatile("cp.async.commit_group;");
            asm volatile("cp.async.wait_group 1;");
        } else {
            asm volatile("cp.async.wait_group 0;");
        }
        __syncthreads();

        const unsigned Asm = smem_u32 + ((ch & 1) * ABUFH) * 2;            // bytes
        const unsigned Bsm = smem_u32 + (2 * ABUFH + (ch & 1) * ABUFH) * 2;

        #pragma unroll
        for (int s = 0; s < 4; s++) {
            const int k0 = s * 16;   // halfs
            unsigned a[4][4], b[2][4];
            #pragma unroll
            for (int im = 0; im < 4; im++) {
                const unsigned addr =
                    Asm + ((wm * 64 + im * 16) * ROWPH + k0 + a_lane) * 2;
                asm volatile(
                    "ldmatrix.sync.aligned.m8n8.x4.shared.b16 {%0,%1,%2,%3}, [%4];"
                    : "=r"(a[im][0]), "=r"(a[im][1]), "=r"(a[im][2]), "=r"(a[im][3])
                    : "r"(addr));
            }
            #pragma unroll
            for (int jp = 0; jp < 2; jp++) {
                const unsigned addr =
                    Bsm + ((wn * 32 + jp * 16) * ROWPH + k0 + b_lane) * 2;
                asm volatile(
                    "ldmatrix.sync.aligned.m8n8.x4.shared.b16 {%0,%1,%2,%3}, [%4];"
                    : "=r"(b[jp][0]), "=r"(b[jp][1]), "=r"(b[jp][2]), "=r"(b[jp][3])
                    : "r"(addr));
            }
            #pragma unroll
            for (int im = 0; im < 4; im++) {
                #pragma unroll
                for (int jn = 0; jn < 4; jn++) {
                    const int jp = jn >> 1;
                    const int lo = (jn & 1) * 2;
                    asm volatile(
                        "mma.sync.aligned.m16n8k16.row.col.f32.f16.f16.f32 "
                        "{%0,%1,%2,%3}, {%4,%5,%6,%7}, {%8,%9}, {%0,%1,%2,%3};"
                        : "+f"(c[im][jn][0]), "+f"(c[im][jn][1]),
                          "+f"(c[im][jn][2]), "+f"(c[im][jn][3])
                        : "r"(a[im][0]), "r"(a[im][1]), "r"(a[im][2]), "r"(a[im][3]),
                          "r"(b[jp][lo]), "r"(b[jp][lo + 1]));
                }
            }
        }
        __syncthreads();
    }

    // Epilogue: float2 stores (C fragment layout identical to k8 tf32 case)
    float* C = out + ((size_t)h * NQ + (size_t)mt * 128) * (size_t)TT + (size_t)nt * 128;
    #pragma unroll
    for (int im = 0; im < 4; im++) {
        const int row = wm * 64 + im * 16 + g;
        #pragma unroll
        for (int jn = 0; jn < 4; jn++) {
            const int col = wn * 32 + jn * 8 + 2 * t4;
            float2 v0; v0.x = c[im][jn][0]; v0.y = c[im][jn][1];
            float2 v1; v1.x = c[im][jn][2]; v1.y = c[im][jn][3];
            *(float2*)(C + (size_t)row * TT + col)       = v0;
            *(float2*)(C + (size_t)(row + 8) * TT + col) = v1;
        }
    }
}

// ---------------------------------------------------------------------------
extern "C" void kernel_launch(void* const* d_in, const int* in_sizes, int n_in,
                              void* d_out, int out_size) {
    const float* q  = (const float*)d_in[0];   // (1,32,2048,128)
    const float* ko = (const float*)d_in[1];   // (1,32,2048,128)
    const float* kq = (const float*)d_in[2];   // (1,32,2048,128)
    const float* G  = (const float*)d_in[3];   // (128,64)
    float* out = (float*)d_out;                // (1,32,2048,2048)

    cudaFuncSetAttribute(prep_mma_kernel,
                         cudaFuncAttributeMaxDynamicSharedMemorySize,
                         PREP_SMEM_BYTES);
    dim3 pgrid(16, 32, 2);
    prep_mma_kernel<<<pgrid, 256, PREP_SMEM_BYTES>>>(q, ko, kq, G);

    cudaFuncSetAttribute(gemm_kernel,
                         cudaFuncAttributeMaxDynamicSharedMemorySize,
                         GEMM_SMEM_BYTES);
    dim3 grid(TT / 128, NQ / 128, HH);
    gemm_kernel<<<grid, 256, GEMM_SMEM_BYTES>>>(out);
}